// round 3
// baseline (speedup 1.0000x reference)
#include <cuda_runtime.h>

#define WIDTH   512
#define HEIGHT  512
#define TH      8                    // output rows per CTA
#define NTH     256                  // threads per CTA
#define GRP     67                   // tuples per t-group (64 data + 3 halo)
#define ROWT    (8 * GRP)            // 536 tuples per SMEM row
#define ROWB    (ROWT * 16)          // 8576 bytes per SMEM row
#define SMEM_BYTES (TH * ROWB)       // 68608

typedef unsigned long long u64;

// reflect padding (pad=3 < dim, single reflection suffices)
__device__ __forceinline__ int refl(int i, int n) {
    i = i < 0 ? -i : i;
    return i >= n ? 2 * n - 2 - i : i;
}

__device__ __forceinline__ u64 pack2(float lo, float hi) {
    u64 r; asm("mov.b64 %0, {%1, %2};" : "=l"(r) : "f"(lo), "f"(hi)); return r;
}
__device__ __forceinline__ void unpack2(u64 v, float& lo, float& hi) {
    asm("mov.b64 {%0, %1}, %2;" : "=f"(lo), "=f"(hi) : "l"(v));
}
// packed dual FMA -> FFMA2 in SASS (PTX-only form)
__device__ __forceinline__ u64 fma2(u64 a, u64 b, u64 c) {
    u64 d; asm("fma.rn.f32x2 %0, %1, %2, %3;" : "=l"(d) : "l"(a), "l"(b), "l"(c));
    return d;
}
__device__ __forceinline__ float fsqrt_ap(float x) {
    float r; asm("sqrt.approx.f32 %0, %1;" : "=f"(r) : "f"(x)); return r;
}
__device__ __forceinline__ float frcp_ap(float x) {
    float r; asm("rcp.approx.f32 %0, %1;" : "=f"(r) : "f"(x)); return r;
}

// t-group layout: pixel x lives at tuple slot (x&7)*GRP + (x>>3) + 1.
// Group g holds slot 0 (low-x halo) and 65,66 spare (high halo uses slot 65
// of groups 0..2). Stage-2 lane l reads slot (l + Cj) with Cj compile-time.

__global__ __launch_bounds__(NTH, 3)
void adain_local_kernel(const float* __restrict__ content,
                        const float* __restrict__ style,
                        float* __restrict__ out) {
    extern __shared__ unsigned char sm[];

    const float G[7] = {0.0044330481752437f, 0.0540055826224143f,
                        0.2420362293761143f, 0.3990502746173879f,
                        0.2420362293761143f, 0.0540055826224143f,
                        0.0044330481752437f};
    u64 G2[7];
    #pragma unroll
    for (int k = 0; k < 7; ++k) G2[k] = pack2(G[k], G[k]);

    const int plane = blockIdx.y;
    const int y0    = blockIdx.x * TH;
    const size_t pb = (size_t)plane * (WIDTH * HEIGHT);
    const float* cp = content + pb;
    const float* sp = style   + pb;
    float*       op = out     + pb;
    const int tid = threadIdx.x;

    const bool interior = (y0 >= 3) && (y0 + TH + 3 <= HEIGHT);

    // -------- Stage 1: vertical 7-tap blur; each thread handles 2 columns ---
    #pragma unroll
    for (int half = 0; half < 2; ++half) {
        const int x = tid + half * NTH;                 // 0..511
        const unsigned sbase = (unsigned)(((x & 7) * GRP + (x >> 3) + 1) * 16);
        // x-halo duplicate slot (reflection pre-applied for stage 2)
        int hs = -1;
        if (x >= 1 && x <= 3)      hs = (8 - x) * GRP * 16;          // low halo
        if (x >= 508 && x <= 510)  hs = ((510 - x) * GRP + 65) * 16; // high halo

        u64 rc[7], rs[7];                               // ring: packed (v, v^2)
        if (interior) {
            const float* crow = cp + (y0 - 3) * WIDTH + x;
            const float* srow = sp + (y0 - 3) * WIDTH + x;
            #pragma unroll
            for (int i = 0; i < TH + 6; ++i) {
                const float c = __ldg(crow + i * WIDTH);   // LDG [R + imm]
                const float s = __ldg(srow + i * WIDTH);
                rc[i % 7] = pack2(c, c * c);
                rs[i % 7] = pack2(s, s * s);
                if (i >= 6) {
                    const int o = i - 6;
                    u64 a = 0ull, d = 0ull;
                    #pragma unroll
                    for (int k = 0; k < 7; ++k) {
                        const int q = (o + k) % 7;         // compile-time
                        a = fma2(G2[k], rc[q], a);
                        d = fma2(G2[k], rs[q], d);
                    }
                    ulonglong2 v; v.x = a; v.y = d;
                    *reinterpret_cast<ulonglong2*>(sm + o * ROWB + sbase) = v;
                    if (hs >= 0)
                        *reinterpret_cast<ulonglong2*>(sm + o * ROWB + hs) = v;
                }
            }
        } else {
            #pragma unroll
            for (int i = 0; i < TH + 6; ++i) {
                const int gy = refl(y0 - 3 + i, HEIGHT);
                const float c = __ldg(cp + gy * WIDTH + x);
                const float s = __ldg(sp + gy * WIDTH + x);
                rc[i % 7] = pack2(c, c * c);
                rs[i % 7] = pack2(s, s * s);
                if (i >= 6) {
                    const int o = i - 6;
                    u64 a = 0ull, d = 0ull;
                    #pragma unroll
                    for (int k = 0; k < 7; ++k) {
                        const int q = (o + k) % 7;
                        a = fma2(G2[k], rc[q], a);
                        d = fma2(G2[k], rs[q], d);
                    }
                    ulonglong2 v; v.x = a; v.y = d;
                    *reinterpret_cast<ulonglong2*>(sm + o * ROWB + sbase) = v;
                    if (hs >= 0)
                        *reinterpret_cast<ulonglong2*>(sm + o * ROWB + hs) = v;
                }
            }
        }
    }
    __syncthreads();

    // ---- Stage 2: horizontal 7-tap + AdaIN epilogue; immediate-offset LDS ---
    // 512 tasks = TH rows x 64 chunks of 8 pixels; 2 tasks per thread.
    #pragma unroll
    for (int t = 0; t < 2; ++t) {
        const int task = tid + t * NTH;
        const int row  = task >> 6;               // 0..TH-1
        const int l    = task & 63;               // chunk id == stage-2 lane
        const int gy   = y0 + row;
        const unsigned char* smrow = sm + row * ROWB + l * 16;

        u64 ac[8], as_[8];
        #pragma unroll
        for (int o = 0; o < 8; ++o) { ac[o] = 0ull; as_[o] = 0ull; }

        #pragma unroll
        for (int j = 0; j < 14; ++j) {
            // window pixel x = 8l + (j-3); slot = l + Cj (Cj compile-time)
            const int Cj = (j < 3)  ? (j + 5) * GRP
                         : (j < 11) ? (j - 3) * GRP + 1
                                    : (j - 11) * GRP + 2;
            const ulonglong2 w =
                *reinterpret_cast<const ulonglong2*>(smrow + Cj * 16);
            #pragma unroll
            for (int o = 0; o < 8; ++o) {
                const int k = j - o;
                if (k >= 0 && k < 7) {            // compile-time predicate
                    ac[o]  = fma2(G2[k], w.x, ac[o]);
                    as_[o] = fma2(G2[k], w.y, as_[o]);
                }
            }
        }

        const int xc = l << 3;
        const float4 cA = *reinterpret_cast<const float4*>(cp + gy * WIDTH + xc);
        const float4 cB = *reinterpret_cast<const float4*>(cp + gy * WIDTH + xc + 4);
        const float craw[8] = {cA.x, cA.y, cA.z, cA.w, cB.x, cB.y, cB.z, cB.w};

        float res[8];
        #pragma unroll
        for (int o = 0; o < 8; ++o) {
            float cm, cv, smn, sv;
            unpack2(ac[o],  cm,  cv);
            unpack2(as_[o], smn, sv);
            const float cvar = fmaxf(fmaf(-cm,  cm,  cv), 0.f);
            const float svar = fmaxf(fmaf(-smn, smn, sv), 0.f);
            const float cstd = fsqrt_ap(cvar) + 1e-5f;
            const float sstd = fsqrt_ap(svar) + 1e-5f;
            const float ratio = sstd * frcp_ap(cstd);
            res[o] = fmaf(craw[o] - cm, ratio, smn);
        }

        *reinterpret_cast<float4*>(op + gy * WIDTH + xc) =
            make_float4(res[0], res[1], res[2], res[3]);
        *reinterpret_cast<float4*>(op + gy * WIDTH + xc + 4) =
            make_float4(res[4], res[5], res[6], res[7]);
    }
}

extern "C" void kernel_launch(void* const* d_in, const int* in_sizes, int n_in,
                              void* d_out, int out_size) {
    const float* content = (const float*)d_in[0];
    const float* style   = (const float*)d_in[1];
    float*       out     = (float*)d_out;

    const int planes = in_sizes[0] / (WIDTH * HEIGHT);   // 4*64 = 256

    cudaFuncSetAttribute(adain_local_kernel,
                         cudaFuncAttributeMaxDynamicSharedMemorySize, SMEM_BYTES);

    dim3 grid(HEIGHT / TH, planes);
    adain_local_kernel<<<grid, NTH, SMEM_BYTES>>>(content, style, out);
}